// round 13
// baseline (speedup 1.0000x reference)
#include <cuda_runtime.h>
#include <cuda_fp16.h>
#include <math.h>
#include <stdint.h>

// ---------------------------------------------------------------------------
// UnifiedAttentionAggregator — fp16 HMMA, N-split 2 CTAs/SM, non-trans ldsm
//   CTA h of a tile computes V-cols [64h,64h+64) and U-cols [128+64h, ...)
//   for 128 rows; gate partial scores summed across h in the bag kernel.
// ---------------------------------------------------------------------------

#define N_INST 524288
#define NF     256
#define L_DIM  128
#define NBAGS  4096
#define NTILES (N_INST / 128)

// smem layout (bytes)
#define OFF_WINS 0
#define OFF_BV   1024
#define OFF_BU   1280
#define OFF_WA   1536
#define OFF_A    2048
#define A_STRIDE 144
#define A_BUF    (128 * A_STRIDE)           // 18432
#define OFF_B    (OFF_A + 2 * A_BUF)        // 38912
#define SM_TOTAL (OFF_B + 128 * 528)        // 106496
#define OFF_C    2048                       // epilogue overlay, stride 544 B

__device__ float g_spart[2][N_INST];
__device__ int   g_offs[NBAGS + 1];
__device__ __align__(16) __half g_Wh[256 * NF];  // [n][k] fp16 (transposed!)

// ---- helpers --------------------------------------------------------------
__device__ __forceinline__ uint32_t smem_u32(const void* p) {
    uint32_t a;
    asm("{ .reg .u64 t; cvta.to.shared.u64 t, %1; cvt.u32.u64 %0, t; }" : "=r"(a) : "l"(p));
    return a;
}
__device__ __forceinline__ uint32_t cvt_h2(float lo, float hi) {
    uint32_t d;
    asm("cvt.rn.f16x2.f32 %0, %1, %2;" : "=r"(d) : "f"(hi), "f"(lo));
    return d;
}
__device__ __forceinline__ void ldsm4(uint32_t& r0, uint32_t& r1, uint32_t& r2, uint32_t& r3,
                                      uint32_t addr) {
    asm volatile("ldmatrix.sync.aligned.m8n8.x4.shared.b16 {%0,%1,%2,%3}, [%4];"
                 : "=r"(r0), "=r"(r1), "=r"(r2), "=r"(r3) : "r"(addr));
}
__device__ __forceinline__ void mma16816(float* c, uint32_t a0, uint32_t a1, uint32_t a2,
                                         uint32_t a3, uint32_t b0, uint32_t b1) {
    asm volatile(
        "mma.sync.aligned.m16n8k16.row.col.f32.f16.f16.f32 "
        "{%0,%1,%2,%3},{%4,%5,%6,%7},{%8,%9},{%0,%1,%2,%3};"
        : "+f"(c[0]), "+f"(c[1]), "+f"(c[2]), "+f"(c[3])
        : "r"(a0), "r"(a1), "r"(a2), "r"(a3), "r"(b0), "r"(b1));
}

// ---------------------------------------------------------------------------
// Kernel 0a: bag-offset scan, shfl-based
// ---------------------------------------------------------------------------
__global__ void scan_kernel(const int* __restrict__ sz32) {
    __shared__ int wsum[32];
    const int t = threadIdx.x, lane = t & 31, w = t >> 5;
    const int stride = (sz32[1] == 0) ? 2 : 1;  // int64 storage detection

    int v[4];
    int s = 0;
#pragma unroll
    for (int j = 0; j < 4; ++j) {
        v[j] = sz32[(4 * t + j) * stride];
        s += v[j];
    }
    const int own = s;
#pragma unroll
    for (int d = 1; d < 32; d <<= 1) {
        int x = __shfl_up_sync(0xffffffffu, s, d);
        if (lane >= d) s += x;
    }
    if (lane == 31) wsum[w] = s;
    __syncthreads();
    if (w == 0) {
        int x = wsum[lane];
#pragma unroll
        for (int d = 1; d < 32; d <<= 1) {
            int y = __shfl_up_sync(0xffffffffu, x, d);
            if (lane >= d) x += y;
        }
        wsum[lane] = x;
    }
    __syncthreads();
    int run = (w ? wsum[w - 1] : 0) + s - own;  // exclusive prefix
#pragma unroll
    for (int j = 0; j < 4; ++j) {
        g_offs[4 * t + j] = run;
        run += v[j];
    }
    if (t == 1023) g_offs[NBAGS] = run;
}

// ---------------------------------------------------------------------------
// Kernel 0b: W -> fp16 [n][k] (transposed for non-trans ldsm B fragments)
// ---------------------------------------------------------------------------
__global__ void wsplit_kernel(const float* __restrict__ W_V,
                              const float* __restrict__ W_U) {
    const int idx = blockIdx.x * 1024 + threadIdx.x;
    const int n = idx >> 8, k = idx & 255;
    float w = (n < L_DIM) ? W_V[k * L_DIM + n] : W_U[k * L_DIM + (n - L_DIM)];
    g_Wh[idx] = __float2half_rn(w);
}

// ---------------------------------------------------------------------------
// Kernel 1: HMMA GEMM. Grid 8192: tile = bid>>1 (128 rows), h = bid&1
// (gate-pair half). Block 256 thr (8 warps 4x2), warp tile 32x64.
// B (128 n-rows x 256 k) resident in smem; A double-buffered; 2 CTAs/SM.
// ---------------------------------------------------------------------------
__global__ __launch_bounds__(256, 2) void gemm_kernel(
    const float* __restrict__ feats,
    const float* __restrict__ W_ins, const float* __restrict__ b_ins,
    const float* __restrict__ b_V, const float* __restrict__ b_U,
    const float* __restrict__ w_att,
    float* __restrict__ out_inst)
{
    extern __shared__ __align__(16) unsigned char sm[];
    const int tid  = threadIdx.x;
    const int wid  = tid >> 5;
    const int lane = tid & 31;
    const int wm   = wid & 3;    // M-warp (32 rows)
    const int wn   = wid >> 2;   // N-warp (64 local cols)
    const int h    = blockIdx.x & 1;
    const int row0 = (blockIdx.x >> 1) * 128;
    const uint32_t smb = smem_u32(sm);

    // consts: biases/weights for this CTA's l-range [64h, 64h+64)
    ((float*)(sm + OFF_WINS))[tid] = W_ins[tid];
    if (tid < 64) {
        ((float*)(sm + OFF_BV))[tid] = b_V[h * 64 + tid];
        ((float*)(sm + OFF_BU))[tid] = b_U[h * 64 + tid];
        ((float*)(sm + OFF_WA))[tid] = w_att[h * 64 + tid];
    }
    // B: 128 n-rows (V half + U half) x 256 k into smem, once
#pragma unroll
    for (int i = 0; i < 16; ++i) {
        const int idx = tid + 256 * i;          // 4096 uint4
        const int r = idx >> 5, q = idx & 31;
        const int n = h * 64 + ((r < 64) ? r : 64 + r);   // global col
        *(uint4*)(sm + OFF_B + r * 528 + q * 16) =
            __ldg(((const uint4*)g_Wh) + n * 32 + q);
    }
    __syncthreads();   // Wins_s/B visible before any thread reads them (race fix)
    const float* Wins_s = (const float*)(sm + OFF_WINS);

    float acc[2][8][4];
#pragma unroll
    for (int mt = 0; mt < 2; ++mt)
#pragma unroll
        for (int nf = 0; nf < 8; ++nf)
#pragma unroll
            for (int j = 0; j < 4; ++j) acc[mt][nf][j] = 0.f;

    const int arow  = tid >> 1;        // 0..127
    const int ahalf = tid & 1;         // 32-k half
    const float* aptr = feats + (size_t)(row0 + arow) * NF + ahalf * 32;
    unsigned char* aDst = sm + OFF_A + arow * A_STRIDE + ahalf * 64;
    float insp = 0.f;

    const uint32_t aBase = smb + OFF_A + (uint32_t)(wm * 32 + (lane & 15)) * A_STRIDE
                         + (uint32_t)(lane >> 4) * 16;
    // non-trans B: lanes 0-15 -> n rows (lane&15), lanes 16-31 -> +16B (k8)
    const uint32_t bBase = smb + OFF_B + (uint32_t)(wn * 64 + (lane & 15)) * 528
                         + (uint32_t)(lane >> 4) * 16;

    // prologue: chunk 0 -> buf 0
    float4 f[8];
#pragma unroll
    for (int q = 0; q < 8; ++q) f[q] = *(const float4*)(aptr + q * 4);
#pragma unroll
    for (int q = 0; q < 8; ++q) {
        const int kk = ahalf * 32 + q * 4;
        insp += f[q].x * Wins_s[kk]     + f[q].y * Wins_s[kk + 1]
              + f[q].z * Wins_s[kk + 2] + f[q].w * Wins_s[kk + 3];
        *(uint2*)(aDst + q * 8) = make_uint2(cvt_h2(f[q].x, f[q].y), cvt_h2(f[q].z, f[q].w));
    }
    __syncthreads();

    for (int c = 0; c < 4; ++c) {
        // prefetch next A chunk (64 k = 8 float4 per thread)
        if (c < 3) {
            const float* ap = aptr + (c + 1) * 64;
#pragma unroll
            for (int q = 0; q < 8; ++q) f[q] = *(const float4*)(ap + q * 4);
        }

        // ---- compute chunk c from buf[c&1] ----
        const uint32_t aBufc = aBase + (uint32_t)(c & 1) * A_BUF;
#pragma unroll
        for (int kt = 0; kt < 4; ++kt) {
            const uint32_t aAddr = aBufc + kt * 32;
            const uint32_t bAddr = bBase + (uint32_t)(c * 128 + kt * 32);
            uint32_t Ah[2][4], B[4][4];

            ldsm4(Ah[0][0], Ah[0][1], Ah[0][2], Ah[0][3], aAddr);
            ldsm4(Ah[1][0], Ah[1][1], Ah[1][2], Ah[1][3], aAddr + 16 * A_STRIDE);
#pragma unroll
            for (int j = 0; j < 4; ++j)   // n-group j*16..+15
                ldsm4(B[j][0], B[j][1], B[j][2], B[j][3], bAddr + j * 16 * 528);
#pragma unroll
            for (int mt = 0; mt < 2; ++mt)
#pragma unroll
                for (int nf = 0; nf < 8; ++nf)
                    mma16816(acc[mt][nf], Ah[mt][0], Ah[mt][1], Ah[mt][2], Ah[mt][3],
                             B[nf >> 1][nf & 1], B[nf >> 1][2 + (nf & 1)]);
        }

        // ---- convert+store next chunk to buf[(c+1)&1] ----
        if (c < 3) {
            unsigned char* dst = aDst + ((c + 1) & 1) * A_BUF;
#pragma unroll
            for (int q = 0; q < 8; ++q) {
                const int kk = (c + 1) * 64 + ahalf * 32 + q * 4;
                insp += f[q].x * Wins_s[kk]     + f[q].y * Wins_s[kk + 1]
                      + f[q].z * Wins_s[kk + 2] + f[q].w * Wins_s[kk + 3];
                *(uint2*)(dst + q * 8) =
                    make_uint2(cvt_h2(f[q].x, f[q].y), cvt_h2(f[q].z, f[q].w));
            }
            __syncthreads();
        }
    }

    // ---- instance predictions (h==0 only) ----
    insp += __shfl_xor_sync(0xffffffffu, insp, 1);
    if (h == 0 && ahalf == 0) out_inst[row0 + arow] = insp + b_ins[0];

    // ---- epilogue: accums -> smem C[128][136 floats], gated partial scores
    __syncthreads();
    {
        const int rbase = wm * 32 + (lane >> 2);
        const int cbase = wn * 64 + (lane & 3) * 2;
#pragma unroll
        for (int mt = 0; mt < 2; ++mt)
#pragma unroll
            for (int nf = 0; nf < 8; ++nf) {
                float* p0 = (float*)(sm + OFF_C + (rbase + mt * 16) * 544
                                     + (cbase + nf * 8) * 4);
                p0[0] = acc[mt][nf][0];
                p0[1] = acc[mt][nf][1];
                float* p1 = (float*)(sm + OFF_C + (rbase + mt * 16 + 8) * 544
                                     + (cbase + nf * 8) * 4);
                p1[0] = acc[mt][nf][2];
                p1[1] = acc[mt][nf][3];
            }
    }
    __syncthreads();
    {
        const float* bV_s = (const float*)(sm + OFF_BV);
        const float* bU_s = (const float*)(sm + OFF_BU);
        const float* wa_s = (const float*)(sm + OFF_WA);
        const unsigned char* crow = sm + OFF_C + arow * 544;
        float part = 0.f;
#pragma unroll
        for (int jj = 0; jj < 8; ++jj) {
            const int j = ahalf * 32 + jj * 4;       // local l index
            float4 v = *(const float4*)(crow + j * 4);
            float4 u = *(const float4*)(crow + (j + 64) * 4);
#pragma unroll
            for (int e = 0; e < 4; ++e) {
                float vv = ((const float*)&v)[e] + bV_s[j + e];
                float uu = ((const float*)&u)[e] + bU_s[j + e];
                float th = 2.f * __fdividef(1.f, 1.f + __expf(-2.f * vv)) - 1.f;
                float sg = __fdividef(1.f, 1.f + __expf(-uu));
                part += th * sg * wa_s[j + e];
            }
        }
        part += __shfl_xor_sync(0xffffffffu, part, 1);
        if (ahalf == 0) g_spart[h][row0 + arow] = part;
    }
}

// ---------------------------------------------------------------------------
// Kernel 2: per-bag segmented softmax + weighted sum (C=1).
// score = spart0 + spart1 (b_att cancels in softmax).
// ---------------------------------------------------------------------------
__global__ void bag_kernel(const float* __restrict__ inst,
                           float* __restrict__ out_bag)
{
    const int b   = blockIdx.x;
    const int tid = threadIdx.x;
    const int s0  = g_offs[b];
    const int s1  = g_offs[b + 1];

    __shared__ float rm[4], re[4], rp[4];

    float m = -3.4e38f;
    for (int i = s0 + tid; i < s1; i += 128)
        m = fmaxf(m, g_spart[0][i] + g_spart[1][i]);
#pragma unroll
    for (int d = 16; d >= 1; d >>= 1)
        m = fmaxf(m, __shfl_xor_sync(0xffffffffu, m, d));
    if ((tid & 31) == 0) rm[tid >> 5] = m;
    __syncthreads();
    m = fmaxf(fmaxf(rm[0], rm[1]), fmaxf(rm[2], rm[3]));

    float se = 0.f, sp = 0.f;
    for (int i = s0 + tid; i < s1; i += 128) {
        float e = expf(g_spart[0][i] + g_spart[1][i] - m);
        se += e;
        sp += e * inst[i];
    }
#pragma unroll
    for (int d = 16; d >= 1; d >>= 1) {
        se += __shfl_xor_sync(0xffffffffu, se, d);
        sp += __shfl_xor_sync(0xffffffffu, sp, d);
    }
    if ((tid & 31) == 0) { re[tid >> 5] = se; rp[tid >> 5] = sp; }
    __syncthreads();
    if (tid == 0) {
        out_bag[b] = (rp[0] + rp[1] + rp[2] + rp[3]) /
                     (re[0] + re[1] + re[2] + re[3]);
    }
}

// ---------------------------------------------------------------------------
extern "C" void kernel_launch(void* const* d_in, const int* in_sizes, int n_in,
                              void* d_out, int out_size)
{
    const float* feats = (const float*)d_in[0];
    const int*   sz32  = (const int*)d_in[1];
    const float* W_ins = (const float*)d_in[2];
    const float* b_ins = (const float*)d_in[3];
    const float* W_V   = (const float*)d_in[4];
    const float* b_V   = (const float*)d_in[5];
    const float* W_U   = (const float*)d_in[6];
    const float* b_U   = (const float*)d_in[7];
    const float* w_att = (const float*)d_in[8];

    float* out      = (float*)d_out;
    float* out_bag  = out;           // [4096]
    float* out_inst = out + NBAGS;   // [524288]

    cudaFuncSetAttribute(gemm_kernel, cudaFuncAttributeMaxDynamicSharedMemorySize, SM_TOTAL);

    scan_kernel<<<1, 1024>>>(sz32);
    wsplit_kernel<<<64, 1024>>>(W_V, W_U);
    gemm_kernel<<<NTILES * 2, 256, SM_TOTAL>>>(feats, W_ins, b_ins, b_V, b_U,
                                               w_att, out_inst);
    bag_kernel<<<NBAGS, 128>>>(out_inst, out_bag);
}

// round 14
// speedup vs baseline: 1.2086x; 1.2086x over previous
#include <cuda_runtime.h>
#include <cuda_fp16.h>
#include <math.h>
#include <stdint.h>

// ---------------------------------------------------------------------------
// UnifiedAttentionAggregator — fp16 HMMA, 8 warps x (64x64) tiles, W resident
//   C[N,256] = feats @ [W_V | W_U]; tile 128x256; A double-buffered.
// ---------------------------------------------------------------------------

#define N_INST 524288
#define NF     256
#define L_DIM  128
#define NBAGS  4096
#define NTILES (N_INST / 128)

// smem layout (bytes)
#define OFF_WINS 0
#define OFF_BV   1024
#define OFF_BU   1536
#define OFF_WA   2048
#define OFF_A    2560
#define A_STRIDE 144
#define A_BUF    (128 * A_STRIDE)           // 18432
#define OFF_B    (OFF_A + 2 * A_BUF)        // 39424
#define SM_TOTAL (OFF_B + 256 * 528)        // 174592
#define OFF_C    2560                       // epilogue overlay, stride 1088 B

__device__ float g_scores[N_INST];
__device__ int   g_offs[NBAGS + 1];
__device__ __align__(16) __half g_Wh[256 * NF];  // [n][k] fp16

// ---- helpers --------------------------------------------------------------
__device__ __forceinline__ uint32_t smem_u32(const void* p) {
    uint32_t a;
    asm("{ .reg .u64 t; cvta.to.shared.u64 t, %1; cvt.u32.u64 %0, t; }" : "=r"(a) : "l"(p));
    return a;
}
__device__ __forceinline__ uint32_t cvt_h2(float lo, float hi) {
    uint32_t d;
    asm("cvt.rn.f16x2.f32 %0, %1, %2;" : "=r"(d) : "f"(hi), "f"(lo));
    return d;
}
__device__ __forceinline__ void ldsm4(uint32_t* r, uint32_t addr) {
    asm volatile("ldmatrix.sync.aligned.m8n8.x4.shared.b16 {%0,%1,%2,%3}, [%4];"
                 : "=r"(r[0]), "=r"(r[1]), "=r"(r[2]), "=r"(r[3]) : "r"(addr));
}
__device__ __forceinline__ void mma16816(float* c, const uint32_t* a,
                                         uint32_t b0, uint32_t b1) {
    asm volatile(
        "mma.sync.aligned.m16n8k16.row.col.f32.f16.f16.f32 "
        "{%0,%1,%2,%3},{%4,%5,%6,%7},{%8,%9},{%0,%1,%2,%3};"
        : "+f"(c[0]), "+f"(c[1]), "+f"(c[2]), "+f"(c[3])
        : "r"(a[0]), "r"(a[1]), "r"(a[2]), "r"(a[3]), "r"(b0), "r"(b1));
}

// ---------------------------------------------------------------------------
// Kernel 0a: bag-offset scan, shfl-based
// ---------------------------------------------------------------------------
__global__ void scan_kernel(const int* __restrict__ sz32) {
    __shared__ int wsum[32];
    const int t = threadIdx.x, lane = t & 31, w = t >> 5;
    const int stride = (sz32[1] == 0) ? 2 : 1;  // int64 storage detection

    int v[4];
    int s = 0;
#pragma unroll
    for (int j = 0; j < 4; ++j) {
        v[j] = sz32[(4 * t + j) * stride];
        s += v[j];
    }
    const int own = s;
#pragma unroll
    for (int d = 1; d < 32; d <<= 1) {
        int x = __shfl_up_sync(0xffffffffu, s, d);
        if (lane >= d) s += x;
    }
    if (lane == 31) wsum[w] = s;
    __syncthreads();
    if (w == 0) {
        int x = wsum[lane];
#pragma unroll
        for (int d = 1; d < 32; d <<= 1) {
            int y = __shfl_up_sync(0xffffffffu, x, d);
            if (lane >= d) x += y;
        }
        wsum[lane] = x;
    }
    __syncthreads();
    int run = (w ? wsum[w - 1] : 0) + s - own;  // exclusive prefix
#pragma unroll
    for (int j = 0; j < 4; ++j) {
        g_offs[4 * t + j] = run;
        run += v[j];
    }
    if (t == 1023) g_offs[NBAGS] = run;
}

// ---------------------------------------------------------------------------
// Kernel 0b: W -> fp16 [n][k]  (non-trans ldsm B fragments)
// ---------------------------------------------------------------------------
__global__ void wsplit_kernel(const float* __restrict__ W_V,
                              const float* __restrict__ W_U) {
    const int idx = blockIdx.x * 1024 + threadIdx.x;
    const int n = idx >> 8, k = idx & 255;
    float w = (n < L_DIM) ? W_V[k * L_DIM + n] : W_U[k * L_DIM + (n - L_DIM)];
    g_Wh[idx] = __float2half_rn(w);
}

// ---------------------------------------------------------------------------
// Kernel 1: HMMA GEMM. Block 256 thr (8 warps, 2x4), warp tile 64x64.
// Tile 128 rows x 256 cols; B (256n x 256k) resident; A double-buffered.
// ---------------------------------------------------------------------------
__global__ __launch_bounds__(256, 1) void gemm_kernel(
    const float* __restrict__ feats,
    const float* __restrict__ W_ins, const float* __restrict__ b_ins,
    const float* __restrict__ b_V, const float* __restrict__ b_U,
    const float* __restrict__ w_att,
    float* __restrict__ out_inst)
{
    extern __shared__ __align__(16) unsigned char sm[];
    const int tid  = threadIdx.x;
    const int wid  = tid >> 5;
    const int lane = tid & 31;
    const int wm   = wid & 1;    // M-warp (64 rows)
    const int wn   = wid >> 1;   // N-warp (64 cols)
    const int row0 = blockIdx.x * 128;
    const uint32_t smb = smem_u32(sm);

    // consts
    ((float*)(sm + OFF_WINS))[tid] = W_ins[tid];
    if (tid < L_DIM) {
        ((float*)(sm + OFF_BV))[tid] = b_V[tid];
        ((float*)(sm + OFF_BU))[tid] = b_U[tid];
        ((float*)(sm + OFF_WA))[tid] = w_att[tid];
    }
    // B: 256 n-rows x 256 k fp16 into smem, once (8192 uint4)
#pragma unroll
    for (int i = 0; i < 32; ++i) {
        const int idx = tid + 256 * i;
        const int r = idx >> 5, q = idx & 31;
        *(uint4*)(sm + OFF_B + r * 528 + q * 16) = __ldg(((const uint4*)g_Wh) + idx);
    }
    __syncthreads();   // consts + B visible before any read
    const float* Wins_s = (const float*)(sm + OFF_WINS);

    float acc[4][8][4];
#pragma unroll
    for (int mt = 0; mt < 4; ++mt)
#pragma unroll
        for (int nf = 0; nf < 8; ++nf)
#pragma unroll
            for (int j = 0; j < 4; ++j) acc[mt][nf][j] = 0.f;

    const int arow  = tid >> 1;        // 0..127
    const int ahalf = tid & 1;         // 32-k half of the 64-k chunk
    const float* aptr = feats + (size_t)(row0 + arow) * NF + ahalf * 32;
    unsigned char* aDst = sm + OFF_A + arow * A_STRIDE + ahalf * 64;
    float insp = 0.f;

    const uint32_t aBase = smb + OFF_A + (uint32_t)(wm * 64 + (lane & 15)) * A_STRIDE
                         + (uint32_t)(lane >> 4) * 16;
    const uint32_t bBase = smb + OFF_B + (uint32_t)(wn * 64 + (lane & 15)) * 528
                         + (uint32_t)(lane >> 4) * 16;

    // prologue: chunk 0 -> buf 0
    {
        float4 f[8];
#pragma unroll
        for (int q = 0; q < 8; ++q) f[q] = *(const float4*)(aptr + q * 4);
#pragma unroll
        for (int q = 0; q < 8; ++q) {
            const int kk = ahalf * 32 + q * 4;
            insp += f[q].x * Wins_s[kk]     + f[q].y * Wins_s[kk + 1]
                  + f[q].z * Wins_s[kk + 2] + f[q].w * Wins_s[kk + 3];
            *(uint2*)(aDst + q * 8) =
                make_uint2(cvt_h2(f[q].x, f[q].y), cvt_h2(f[q].z, f[q].w));
        }
    }
    __syncthreads();

    float4 f[8];
    for (int c = 0; c < 4; ++c) {
        const uint32_t aBufc = aBase + (uint32_t)(c & 1) * A_BUF;

        // ---- kt 0, then issue next-chunk prefetch, then kt 1..3 ----
#pragma unroll
        for (int kt = 0; kt < 4; ++kt) {
            const uint32_t aAddr = aBufc + kt * 32;
            const uint32_t bAddr = bBase + (uint32_t)(c * 128 + kt * 32);
            uint32_t Af[4][4], Bf[4][4];
#pragma unroll
            for (int mt = 0; mt < 4; ++mt) ldsm4(Af[mt], aAddr + mt * 16 * A_STRIDE);
#pragma unroll
            for (int j = 0; j < 4; ++j)  ldsm4(Bf[j], bAddr + (uint32_t)(j * 16 * 528));
#pragma unroll
            for (int mt = 0; mt < 4; ++mt)
#pragma unroll
                for (int nf = 0; nf < 8; ++nf)
                    mma16816(acc[mt][nf], Af[mt],
                             Bf[nf >> 1][nf & 1], Bf[nf >> 1][2 + (nf & 1)]);

            if (kt == 0 && c < 3) {
                const float* ap = aptr + (c + 1) * 64;
#pragma unroll
                for (int q = 0; q < 8; ++q) f[q] = *(const float4*)(ap + q * 4);
            }
        }

        // ---- convert+store next chunk to buf[(c+1)&1] ----
        if (c < 3) {
            unsigned char* dst = aDst + ((c + 1) & 1) * A_BUF;
#pragma unroll
            for (int q = 0; q < 8; ++q) {
                const int kk = (c + 1) * 64 + ahalf * 32 + q * 4;
                insp += f[q].x * Wins_s[kk]     + f[q].y * Wins_s[kk + 1]
                      + f[q].z * Wins_s[kk + 2] + f[q].w * Wins_s[kk + 3];
                *(uint2*)(dst + q * 8) =
                    make_uint2(cvt_h2(f[q].x, f[q].y), cvt_h2(f[q].z, f[q].w));
            }
            __syncthreads();
        }
    }

    // ---- instance predictions ----
    insp += __shfl_xor_sync(0xffffffffu, insp, 1);
    if (ahalf == 0) out_inst[row0 + arow] = insp + b_ins[0];

    // ---- epilogue: accums -> smem C[128][272 floats], gated scores ----
    __syncthreads();
    {
        const int rbase = wm * 64 + (lane >> 2);
        const int cbase = wn * 64 + (lane & 3) * 2;
#pragma unroll
        for (int mt = 0; mt < 4; ++mt)
#pragma unroll
            for (int nf = 0; nf < 8; ++nf) {
                float* p0 = (float*)(sm + OFF_C + (rbase + mt * 16) * 1088
                                     + (cbase + nf * 8) * 4);
                p0[0] = acc[mt][nf][0];
                p0[1] = acc[mt][nf][1];
                float* p1 = (float*)(sm + OFF_C + (rbase + mt * 16 + 8) * 1088
                                     + (cbase + nf * 8) * 4);
                p1[0] = acc[mt][nf][2];
                p1[1] = acc[mt][nf][3];
            }
    }
    __syncthreads();
    {
        const float* bV_s = (const float*)(sm + OFF_BV);
        const float* bU_s = (const float*)(sm + OFF_BU);
        const float* wa_s = (const float*)(sm + OFF_WA);
        const unsigned char* crow = sm + OFF_C + arow * 1088;
        float part = 0.f;
#pragma unroll
        for (int jj = 0; jj < 16; ++jj) {
            const int l = ahalf * 64 + jj * 4;
            float4 v = *(const float4*)(crow + l * 4);
            float4 u = *(const float4*)(crow + (l + L_DIM) * 4);
#pragma unroll
            for (int e = 0; e < 4; ++e) {
                float vv = ((const float*)&v)[e] + bV_s[l + e];
                float uu = ((const float*)&u)[e] + bU_s[l + e];
                float th = 2.f * __fdividef(1.f, 1.f + __expf(-2.f * vv)) - 1.f;
                float sg = __fdividef(1.f, 1.f + __expf(-uu));
                part += th * sg * wa_s[l + e];
            }
        }
        part += __shfl_xor_sync(0xffffffffu, part, 1);
        if (ahalf == 0) g_scores[row0 + arow] = part;
    }
}

// ---------------------------------------------------------------------------
// Kernel 2: per-bag segmented softmax + weighted sum (C=1).
// (b_att omitted from scores: constant shift cancels in softmax.)
// ---------------------------------------------------------------------------
__global__ void bag_kernel(const float* __restrict__ inst,
                           float* __restrict__ out_bag)
{
    const int b   = blockIdx.x;
    const int tid = threadIdx.x;
    const int s0  = g_offs[b];
    const int s1  = g_offs[b + 1];

    __shared__ float rm[4], re[4], rp[4];

    float m = -3.4e38f;
    for (int i = s0 + tid; i < s1; i += 128) m = fmaxf(m, g_scores[i]);
#pragma unroll
    for (int d = 16; d >= 1; d >>= 1)
        m = fmaxf(m, __shfl_xor_sync(0xffffffffu, m, d));
    if ((tid & 31) == 0) rm[tid >> 5] = m;
    __syncthreads();
    m = fmaxf(fmaxf(rm[0], rm[1]), fmaxf(rm[2], rm[3]));

    float se = 0.f, sp = 0.f;
    for (int i = s0 + tid; i < s1; i += 128) {
        float e = expf(g_scores[i] - m);
        se += e;
        sp += e * inst[i];
    }
#pragma unroll
    for (int d = 16; d >= 1; d >>= 1) {
        se += __shfl_xor_sync(0xffffffffu, se, d);
        sp += __shfl_xor_sync(0xffffffffu, sp, d);
    }
    if ((tid & 31) == 0) { re[tid >> 5] = se; rp[tid >> 5] = sp; }
    __syncthreads();
    if (tid == 0) {
        out_bag[b] = (rp[0] + rp[1] + rp[2] + rp[3]) /
                     (re[0] + re[1] + re[2] + re[3]);
    }
}

// ---------------------------------------------------------------------------
extern "C" void kernel_launch(void* const* d_in, const int* in_sizes, int n_in,
                              void* d_out, int out_size)
{
    const float* feats = (const float*)d_in[0];
    const int*   sz32  = (const int*)d_in[1];
    const float* W_ins = (const float*)d_in[2];
    const float* b_ins = (const float*)d_in[3];
    const float* W_V   = (const float*)d_in[4];
    const float* b_V   = (const float*)d_in[5];
    const float* W_U   = (const float*)d_in[6];
    const float* b_U   = (const float*)d_in[7];
    const float* w_att = (const float*)d_in[8];

    float* out      = (float*)d_out;
    float* out_bag  = out;           // [4096]
    float* out_inst = out + NBAGS;   // [524288]

    cudaFuncSetAttribute(gemm_kernel, cudaFuncAttributeMaxDynamicSharedMemorySize, SM_TOTAL);

    scan_kernel<<<1, 1024>>>(sz32);
    wsplit_kernel<<<64, 1024>>>(W_V, W_U);
    gemm_kernel<<<NTILES, 256, SM_TOTAL>>>(feats, W_ins, b_ins, b_V, b_U,
                                           w_att, out_inst);
    bag_kernel<<<NBAGS, 128>>>(out_inst, out_bag);
}

// round 16
// speedup vs baseline: 1.5079x; 1.2476x over previous
#include <cuda_runtime.h>
#include <cuda_fp16.h>
#include <math.h>
#include <stdint.h>

// ---------------------------------------------------------------------------
// UnifiedAttentionAggregator — fp16 HMMA (R8 skeleton) + non-trans ldsm B
//   C[N,256] = feats @ [W_V | W_U]; tile 128x256; 512 thr; W smem-resident.
// ---------------------------------------------------------------------------

#define N_INST 524288
#define NF     256
#define L_DIM  128
#define NBAGS  4096
#define NTILES (N_INST / 128)

// smem layout (bytes)
#define OFF_WINS 0
#define OFF_BV   1024
#define OFF_BU   1536
#define OFF_WA   2048
#define OFF_A    2560
#define A_STRIDE 144
#define A_BUF    (128 * A_STRIDE)           // 18432
#define OFF_B    (OFF_A + 2 * A_BUF)        // 39424
#define SM_TOTAL (OFF_B + 256 * 528)        // 174592
#define OFF_C    2560                       // epilogue overlay, stride 1088 B

__device__ float g_scores[N_INST];
__device__ int   g_offs[NBAGS + 1];
__device__ __align__(16) __half g_Wh[256 * NF];  // [n][k] fp16

// ---- helpers --------------------------------------------------------------
__device__ __forceinline__ uint32_t smem_u32(const void* p) {
    uint32_t a;
    asm("{ .reg .u64 t; cvta.to.shared.u64 t, %1; cvt.u32.u64 %0, t; }" : "=r"(a) : "l"(p));
    return a;
}
__device__ __forceinline__ uint32_t cvt_h2(float lo, float hi) {
    uint32_t d;
    asm("cvt.rn.f16x2.f32 %0, %1, %2;" : "=r"(d) : "f"(hi), "f"(lo));
    return d;
}
__device__ __forceinline__ void ldsm4(uint32_t* r, uint32_t addr) {
    asm volatile("ldmatrix.sync.aligned.m8n8.x4.shared.b16 {%0,%1,%2,%3}, [%4];"
                 : "=r"(r[0]), "=r"(r[1]), "=r"(r[2]), "=r"(r[3]) : "r"(addr));
}
__device__ __forceinline__ void mma16816(float* c, const uint32_t* a,
                                         uint32_t b0, uint32_t b1) {
    asm volatile(
        "mma.sync.aligned.m16n8k16.row.col.f32.f16.f16.f32 "
        "{%0,%1,%2,%3},{%4,%5,%6,%7},{%8,%9},{%0,%1,%2,%3};"
        : "+f"(c[0]), "+f"(c[1]), "+f"(c[2]), "+f"(c[3])
        : "r"(a[0]), "r"(a[1]), "r"(a[2]), "r"(a[3]), "r"(b0), "r"(b1));
}

// ---------------------------------------------------------------------------
// Kernel 0a: bag-offset scan, shfl-based
// ---------------------------------------------------------------------------
__global__ void scan_kernel(const int* __restrict__ sz32) {
    __shared__ int wsum[32];
    const int t = threadIdx.x, lane = t & 31, w = t >> 5;
    const int stride = (sz32[1] == 0) ? 2 : 1;  // int64 storage detection

    int v[4];
    int s = 0;
#pragma unroll
    for (int j = 0; j < 4; ++j) {
        v[j] = sz32[(4 * t + j) * stride];
        s += v[j];
    }
    const int own = s;
#pragma unroll
    for (int d = 1; d < 32; d <<= 1) {
        int x = __shfl_up_sync(0xffffffffu, s, d);
        if (lane >= d) s += x;
    }
    if (lane == 31) wsum[w] = s;
    __syncthreads();
    if (w == 0) {
        int x = wsum[lane];
#pragma unroll
        for (int d = 1; d < 32; d <<= 1) {
            int y = __shfl_up_sync(0xffffffffu, x, d);
            if (lane >= d) x += y;
        }
        wsum[lane] = x;
    }
    __syncthreads();
    int run = (w ? wsum[w - 1] : 0) + s - own;  // exclusive prefix
#pragma unroll
    for (int j = 0; j < 4; ++j) {
        g_offs[4 * t + j] = run;
        run += v[j];
    }
    if (t == 1023) g_offs[NBAGS] = run;
}

// ---------------------------------------------------------------------------
// Kernel 0b: W -> fp16 [n][k]  (non-trans ldsm B fragments)
// ---------------------------------------------------------------------------
__global__ void wsplit_kernel(const float* __restrict__ W_V,
                              const float* __restrict__ W_U) {
    const int idx = blockIdx.x * 1024 + threadIdx.x;
    const int n = idx >> 8, k = idx & 255;
    float w = (n < L_DIM) ? W_V[k * L_DIM + n] : W_U[k * L_DIM + (n - L_DIM)];
    g_Wh[idx] = __float2half_rn(w);
}

// ---------------------------------------------------------------------------
// Kernel 1: HMMA GEMM. Block 512 thr (16 warps 4x4), warp tile 32x64.
// Tile 128 rows x 256 cols; B (256n x 256k) resident; A double-buffered.
// ---------------------------------------------------------------------------
__global__ __launch_bounds__(512, 1) void gemm_kernel(
    const float* __restrict__ feats,
    const float* __restrict__ W_ins, const float* __restrict__ b_ins,
    const float* __restrict__ b_V, const float* __restrict__ b_U,
    const float* __restrict__ w_att,
    float* __restrict__ out_inst)
{
    extern __shared__ __align__(16) unsigned char sm[];
    const int tid  = threadIdx.x;
    const int wid  = tid >> 5;
    const int lane = tid & 31;
    const int wm   = wid & 3;    // M-warp (32 rows)
    const int wn   = wid >> 2;   // N-warp (64 cols)
    const int row0 = blockIdx.x * 128;
    const uint32_t smb = smem_u32(sm);

    // consts
    if (tid < 256) ((float*)(sm + OFF_WINS))[tid] = W_ins[tid];
    if (tid < L_DIM) {
        ((float*)(sm + OFF_BV))[tid] = b_V[tid];
        ((float*)(sm + OFF_BU))[tid] = b_U[tid];
        ((float*)(sm + OFF_WA))[tid] = w_att[tid];
    }
    // B: 256 n-rows x 256 k fp16 into smem, once (8192 uint4)
#pragma unroll
    for (int i = 0; i < 16; ++i) {
        const int idx = tid + 512 * i;
        const int r = idx >> 5, q = idx & 31;
        *(uint4*)(sm + OFF_B + r * 528 + q * 16) = __ldg(((const uint4*)g_Wh) + idx);
    }
    __syncthreads();   // consts + B visible before any read
    const float* Wins_s = (const float*)(sm + OFF_WINS);

    float acc[2][8][4];
#pragma unroll
    for (int mt = 0; mt < 2; ++mt)
#pragma unroll
        for (int nf = 0; nf < 8; ++nf)
#pragma unroll
            for (int j = 0; j < 4; ++j) acc[mt][nf][j] = 0.f;

    const int arow = tid >> 2;         // 0..127
    const int akq  = tid & 3;          // 16-k quarter of the 64-k chunk
    const float* aptr = feats + (size_t)(row0 + arow) * NF + akq * 16;
    unsigned char* aDst = sm + OFF_A + arow * A_STRIDE + akq * 32;
    float insp = 0.f;

    const uint32_t aBase = smb + OFF_A + (uint32_t)(wm * 32 + (lane & 15)) * A_STRIDE
                         + (uint32_t)(lane >> 4) * 16;
    // non-trans B: lanes 0-15 -> n-rows, lanes 16-31 -> +16 B (k8 offset)
    const uint32_t bBase = smb + OFF_B + (uint32_t)(wn * 64 + (lane & 15)) * 528
                         + (uint32_t)(lane >> 4) * 16;

    // prologue: chunk 0 -> buf 0
    float4 f[4];
#pragma unroll
    for (int q = 0; q < 4; ++q) f[q] = *(const float4*)(aptr + q * 4);
#pragma unroll
    for (int q = 0; q < 4; ++q) {
        const int kk = akq * 16 + q * 4;
        insp += f[q].x * Wins_s[kk]     + f[q].y * Wins_s[kk + 1]
              + f[q].z * Wins_s[kk + 2] + f[q].w * Wins_s[kk + 3];
        *(uint2*)(aDst + q * 8) = make_uint2(cvt_h2(f[q].x, f[q].y), cvt_h2(f[q].z, f[q].w));
    }
    __syncthreads();

    for (int c = 0; c < 4; ++c) {
        // prefetch next A chunk into registers (hidden under compute)
        if (c < 3) {
            const float* ap = aptr + (c + 1) * 64;
#pragma unroll
            for (int q = 0; q < 4; ++q) f[q] = *(const float4*)(ap + q * 4);
        }

        // ---- compute chunk c from buf[c&1] ----
        const uint32_t aBufc = aBase + (uint32_t)(c & 1) * A_BUF;
#pragma unroll
        for (int kt = 0; kt < 4; ++kt) {
            const uint32_t aAddr = aBufc + kt * 32;
            const uint32_t bAddr = bBase + (uint32_t)(c * 128 + kt * 32);
            uint32_t Ah[2][4], Bf[4][4];

            ldsm4(Ah[0], aAddr);
            ldsm4(Ah[1], aAddr + 16 * A_STRIDE);
#pragma unroll
            for (int j = 0; j < 4; ++j)   // n-group j: rows wn*64+j*16..+15
                ldsm4(Bf[j], bAddr + (uint32_t)(j * 16 * 528));
#pragma unroll
            for (int mt = 0; mt < 2; ++mt)
#pragma unroll
                for (int nf = 0; nf < 8; ++nf)
                    mma16816(acc[mt][nf], Ah[mt],
                             Bf[nf >> 1][nf & 1], Bf[nf >> 1][2 + (nf & 1)]);
        }

        // ---- convert+store next chunk to buf[(c+1)&1] ----
        if (c < 3) {
            unsigned char* dst = aDst + ((c + 1) & 1) * A_BUF;
#pragma unroll
            for (int q = 0; q < 4; ++q) {
                const int kk = (c + 1) * 64 + akq * 16 + q * 4;
                insp += f[q].x * Wins_s[kk]     + f[q].y * Wins_s[kk + 1]
                      + f[q].z * Wins_s[kk + 2] + f[q].w * Wins_s[kk + 3];
                *(uint2*)(dst + q * 8) =
                    make_uint2(cvt_h2(f[q].x, f[q].y), cvt_h2(f[q].z, f[q].w));
            }
            __syncthreads();
        }
    }

    // ---- instance predictions ----
    insp += __shfl_xor_sync(0xffffffffu, insp, 1);
    insp += __shfl_xor_sync(0xffffffffu, insp, 2);
    if (akq == 0) out_inst[row0 + arow] = insp + b_ins[0];

    // ---- epilogue: accums -> smem C[128][272 floats], gated scores ----
    __syncthreads();
    {
        const int rbase = wm * 32 + (lane >> 2);
        const int cbase = wn * 64 + (lane & 3) * 2;
#pragma unroll
        for (int mt = 0; mt < 2; ++mt)
#pragma unroll
            for (int nf = 0; nf < 8; ++nf) {
                float* p0 = (float*)(sm + OFF_C + (rbase + mt * 16) * 1088
                                     + (cbase + nf * 8) * 4);
                p0[0] = acc[mt][nf][0];
                p0[1] = acc[mt][nf][1];
                float* p1 = (float*)(sm + OFF_C + (rbase + mt * 16 + 8) * 1088
                                     + (cbase + nf * 8) * 4);
                p1[0] = acc[mt][nf][2];
                p1[1] = acc[mt][nf][3];
            }
    }
    __syncthreads();
    {
        const float* bV_s = (const float*)(sm + OFF_BV);
        const float* bU_s = (const float*)(sm + OFF_BU);
        const float* wa_s = (const float*)(sm + OFF_WA);
        const unsigned char* crow = sm + OFF_C + arow * 1088;
        float part = 0.f;
#pragma unroll
        for (int jj = 0; jj < 8; ++jj) {
            const int l = jj * 16 + akq * 4;
            float4 v = *(const float4*)(crow + l * 4);
            float4 u = *(const float4*)(crow + (l + L_DIM) * 4);
#pragma unroll
            for (int e = 0; e < 4; ++e) {
                float vv = ((const float*)&v)[e] + bV_s[l + e];
                float uu = ((const float*)&u)[e] + bU_s[l + e];
                float th = 2.f * __fdividef(1.f, 1.f + __expf(-2.f * vv)) - 1.f;
                float sg = __fdividef(1.f, 1.f + __expf(-uu));
                part += th * sg * wa_s[l + e];
            }
        }
        part += __shfl_xor_sync(0xffffffffu, part, 1);
        part += __shfl_xor_sync(0xffffffffu, part, 2);
        if (akq == 0) g_scores[row0 + arow] = part;
    }
}

// ---------------------------------------------------------------------------
// Kernel 2: per-bag segmented softmax + weighted sum (C=1).
// (b_att omitted: constant shift cancels in softmax.)
// ---------------------------------------------------------------------------
__global__ void bag_kernel(const float* __restrict__ inst,
                           float* __restrict__ out_bag)
{
    const int b   = blockIdx.x;
    const int tid = threadIdx.x;
    const int s0  = g_offs[b];
    const int s1  = g_offs[b + 1];

    __shared__ float rm[4], re[4], rp[4];

    float m = -3.4e38f;
    for (int i = s0 + tid; i < s1; i += 128) m = fmaxf(m, g_scores[i]);
#pragma unroll
    for (int d = 16; d >= 1; d >>= 1)
        m = fmaxf(m, __shfl_xor_sync(0xffffffffu, m, d));
    if ((tid & 31) == 0) rm[tid >> 5] = m;
    __syncthreads();
    m = fmaxf(fmaxf(rm[0], rm[1]), fmaxf(rm[2], rm[3]));

    float se = 0.f, sp = 0.f;
    for (int i = s0 + tid; i < s1; i += 128) {
        float e = expf(g_scores[i] - m);
        se += e;
        sp += e * inst[i];
    }
#pragma unroll
    for (int d = 16; d >= 1; d >>= 1) {
        se += __shfl_xor_sync(0xffffffffu, se, d);
        sp += __shfl_xor_sync(0xffffffffu, sp, d);
    }
    if ((tid & 31) == 0) { re[tid >> 5] = se; rp[tid >> 5] = sp; }
    __syncthreads();
    if (tid == 0) {
        out_bag[b] = (rp[0] + rp[1] + rp[2] + rp[3]) /
                     (re[0] + re[1] + re[2] + re[3]);
    }
}

// ---------------------------------------------------------------------------
extern "C" void kernel_launch(void* const* d_in, const int* in_sizes, int n_in,
                              void* d_out, int out_size)
{
    const float* feats = (const float*)d_in[0];
    const int*   sz32  = (const int*)d_in[1];
    const float* W_ins = (const float*)d_in[2];
    const float* b_ins = (const float*)d_in[3];
    const float* W_V   = (const float*)d_in[4];
    const float* b_V   = (const float*)d_in[5];
    const float* W_U   = (const float*)d_in[6];
    const float* b_U   = (const float*)d_in[7];
    const float* w_att = (const float*)d_in[8];

    float* out      = (float*)d_out;
    float* out_bag  = out;           // [4096]
    float* out_inst = out + NBAGS;   // [524288]

    cudaFuncSetAttribute(gemm_kernel, cudaFuncAttributeMaxDynamicSharedMemorySize, SM_TOTAL);

    scan_kernel<<<1, 1024>>>(sz32);
    wsplit_kernel<<<64, 1024>>>(W_V, W_U);
    gemm_kernel<<<NTILES, 512, SM_TOTAL>>>(feats, W_ins, b_ins, b_V, b_U,
                                           w_att, out_inst);
    bag_kernel<<<NBAGS, 128>>>(out_inst, out_bag);
}